// round 15
// baseline (speedup 1.0000x reference)
#include <cuda_runtime.h>
#include <cuda_fp16.h>
#include <cstdint>

// Problem constants
#define T_TOK   32768        // 8*64*64 tokens
#define DIM     768
#define DIM3    2304
#define HEADS   12
#define HD      64
#define NCHUNK  12           // 768 / 64 (K chunks per tile row)
#define TILE_BYTES 16384     // 128 rows x 64 fp16 x 2B
#define STAGE_BYTES 32768    // A tile + B tile
#define NSTAGE  3
// proj (BN=64) variant
#define STAGE_BYTES64 24576  // A tile (16KB) + B half-tile (8KB)

// Scratch (fp16 tiled/swizzled)
__device__ uint8_t g_A  [(size_t)(T_TOK/128) * NCHUNK * TILE_BYTES];  // x tiles, 50MB
__device__ uint8_t g_Bh [(size_t)(DIM3/128) * NCHUNK * TILE_BYTES];   // 3.4MB
__device__ uint8_t g_Bw [(size_t)(DIM3/128) * NCHUNK * TILE_BYTES];
__device__ uint8_t g_Bp [(size_t)(DIM/128) * NCHUNK * TILE_BYTES];    // 1.2MB
__device__ uint8_t g_qkvh[(size_t)(T_TOK/128) * 36 * TILE_BYTES];     // 151MB
__device__ uint8_t g_qkvw[(size_t)(T_TOK/128) * 36 * TILE_BYTES];     // 151MB
__device__ uint8_t g_Ao [(size_t)(T_TOK/128) * NCHUNK * TILE_BYTES];  // attn out, 50MB

// ---------------------------------------------------------------------------
// PTX helpers (base-target only: ldmatrix / mma.sync / cp.async)
// ---------------------------------------------------------------------------
__device__ __forceinline__ uint32_t smem_u32(const void* p) {
    uint32_t a;
    asm("{ .reg .u64 t; cvta.to.shared.u64 t, %1; cvt.u32.u64 %0, t; }"
        : "=r"(a) : "l"(p));
    return a;
}

__device__ __forceinline__ void ldsm_x4(uint32_t* r, uint32_t addr) {
    asm volatile("ldmatrix.sync.aligned.m8n8.x4.shared.b16 {%0,%1,%2,%3}, [%4];"
                 : "=r"(r[0]), "=r"(r[1]), "=r"(r[2]), "=r"(r[3]) : "r"(addr));
}

__device__ __forceinline__ void ldsm_x4t(uint32_t* r, uint32_t addr) {
    asm volatile("ldmatrix.sync.aligned.m8n8.x4.trans.shared.b16 {%0,%1,%2,%3}, [%4];"
                 : "=r"(r[0]), "=r"(r[1]), "=r"(r[2]), "=r"(r[3]) : "r"(addr));
}

__device__ __forceinline__ void mma_f16(float* d, const uint32_t* a, const uint32_t* b) {
    asm volatile(
        "mma.sync.aligned.m16n8k16.row.col.f32.f16.f16.f32 "
        "{%0,%1,%2,%3}, {%4,%5,%6,%7}, {%8,%9}, {%0,%1,%2,%3};"
        : "+f"(d[0]), "+f"(d[1]), "+f"(d[2]), "+f"(d[3])
        : "r"(a[0]), "r"(a[1]), "r"(a[2]), "r"(a[3]), "r"(b[0]), "r"(b[1]));
}

__device__ __forceinline__ void cp16(uint32_t smem, const void* gmem) {
    asm volatile("cp.async.cg.shared.global [%0], [%1], 16;"
                 :: "r"(smem), "l"(gmem) : "memory");
}
__device__ __forceinline__ void cp4(uint32_t smem, const void* gmem) {
    asm volatile("cp.async.ca.shared.global [%0], [%1], 4;"
                 :: "r"(smem), "l"(gmem) : "memory");
}
#define CP_COMMIT() asm volatile("cp.async.commit_group;" ::: "memory")
#define CP_WAIT(n)  asm volatile("cp.async.wait_group %0;" :: "n"(n) : "memory")

__device__ __forceinline__ uint32_t h2u(float x, float y) {
    __half2 h = __floats2half2_rn(x, y);
    return *(uint32_t*)&h;
}

// ---------------------------------------------------------------------------
// Converts: fp32 -> fp16, pre-tiled 16KB blocks, SW128-style swizzle:
// off(r, c16) = (r*128 + c16*16) ^ ((r&7)<<4). Tile = 128 rows x 64 fp16.
// All four converts fused into ONE launch, dispatched by blockIdx range.
// ---------------------------------------------------------------------------
union HF8 { __half h[8]; uint4 u; };

__device__ __forceinline__ void conv_a_body(
    int idx, const float* __restrict__ in, uint8_t* __restrict__ dst)
{
    int m = idx / 96;                               // 96 units per row (768/8)
    int u = idx - m * 96;
    const float* p = in + (size_t)m * DIM + u * 8;
    float4 v0 = *(const float4*)p;
    float4 v1 = *(const float4*)(p + 4);
    float f[8] = {v0.x, v0.y, v0.z, v0.w, v1.x, v1.y, v1.z, v1.w};
    HF8 h;
    #pragma unroll
    for (int i = 0; i < 8; i++) h.h[i] = __float2half_rn(f[i]);
    int mtile = m >> 7, r = m & 127, chunk = u >> 3, c16 = u & 7;
    uint32_t off = (uint32_t)(r * 128 + c16 * 16) ^ (uint32_t)((r & 7) << 4);
    *(uint4*)(dst + (size_t)(mtile * NCHUNK + chunk) * TILE_BYTES + off) = h.u;
}

__device__ __forceinline__ void conv_b_body(
    int idx, const float* __restrict__ w, uint8_t* __restrict__ dst, int N)
{
    int n = idx / 96;
    int u = idx - n * 96;
    int k0 = u * 8;
    HF8 h;
    #pragma unroll
    for (int i = 0; i < 8; i++)
        h.h[i] = __float2half_rn(w[(size_t)(k0 + i) * N + n]);
    int ntile = n >> 7, r = n & 127, chunk = u >> 3, c16 = u & 7;
    uint32_t off = (uint32_t)(r * 128 + c16 * 16) ^ (uint32_t)((r & 7) << 4);
    *(uint4*)(dst + (size_t)(ntile * NCHUNK + chunk) * TILE_BYTES + off) = h.u;
}

// blocks: [0,12288) A | [12288,13152) Bh | [13152,14016) Bw | [14016,14304) Bp
__global__ __launch_bounds__(256) void conv_all(
    const float* __restrict__ x,
    const float* __restrict__ w_qkv_h, const float* __restrict__ w_qkv_w,
    const float* __restrict__ w_proj,
    uint8_t* __restrict__ A, uint8_t* __restrict__ Bh,
    uint8_t* __restrict__ Bw, uint8_t* __restrict__ Bp)
{
    int b = blockIdx.x;
    if (b < 12288) {
        conv_a_body(b * 256 + threadIdx.x, x, A);
    } else if (b < 13152) {
        conv_b_body((b - 12288) * 256 + threadIdx.x, w_qkv_h, Bh, DIM3);
    } else if (b < 14016) {
        conv_b_body((b - 13152) * 256 + threadIdx.x, w_qkv_w, Bw, DIM3);
    } else {
        conv_b_body((b - 14016) * 256 + threadIdx.x, w_proj, Bp, DIM);
    }
}

// ---------------------------------------------------------------------------
// HMMA GEMM (round-10 verified-best, byte-frozen): C = A @ B^T + bias
// BM=BN=128, 256 threads = 8 warps in 4(M) x 2(N), warp tile 32 x 64.
// 3-stage cp.async pipeline, ONE __syncthreads per chunk, 96KB, 2 CTA/SM.
// fp16 tiled+swizzled output; dual-output QKV mode via nsplit.
// ---------------------------------------------------------------------------
__global__ __launch_bounds__(256, 2) void gemm_hmma_qkv(
    const uint8_t* __restrict__ A,
    const uint8_t* __restrict__ B,  const float* __restrict__ bias,  void* Cout,
    const uint8_t* __restrict__ B2, const float* __restrict__ bias2, void* Cout2,
    int N, int nsplit)
{
    extern __shared__ uint8_t smem[];
    const uint32_t sb = smem_u32(smem);

    const int tid  = threadIdx.x;
    const int lane = tid & 31;
    const int wid  = tid >> 5;
    const int wm   = wid >> 1;          // 0..3 -> M (32 rows each)
    const int wn   = wid & 1;           // 0..1 -> N (64 cols each)

    int tile_n = blockIdx.x;
    const int tile_m = blockIdx.y;
    if (tile_n >= nsplit) { tile_n -= nsplit; B = B2; bias = bias2; Cout = Cout2; }

    const size_t a0 = (size_t)tile_m * NCHUNK * TILE_BYTES;
    const size_t b0 = (size_t)tile_n * NCHUNK * TILE_BYTES;

    const uint32_t cp_off = (uint32_t)tid * 16;

    const uint32_t sx   = (uint32_t)((lane & 7) << 4);
    const uint32_t a_r  = (uint32_t)(((lane >> 3) & 1) * 8 + (lane & 7));
    const uint32_t a_cg = (uint32_t)(lane >> 4);
    const uint32_t b_r  = (uint32_t)(((lane >> 4) & 1) * 8 + (lane & 7));
    const uint32_t b_cg = (uint32_t)((lane >> 3) & 1);

    float acc[2][8][4];
    #pragma unroll
    for (int i = 0; i < 2; i++)
        #pragma unroll
        for (int j = 0; j < 8; j++)
            #pragma unroll
            for (int q = 0; q < 4; q++) acc[i][j][q] = 0.0f;

    auto load_stage = [&](int s, int c) {
        uint32_t st = sb + (uint32_t)s * STAGE_BYTES;
        size_t ko = (size_t)c * TILE_BYTES;
        #pragma unroll
        for (int q = 0; q < 4; q++) {
            uint32_t o = cp_off + (uint32_t)q * 4096;
            cp16(st +         o, A + a0 + ko + o);
            cp16(st + 16384 + o, B + b0 + ko + o);
        }
        CP_COMMIT();
    };

    load_stage(0, 0);
    load_stage(1, 1);

    for (int c = 0; c < NCHUNK; c++) {
        if (c < NCHUNK - 1) CP_WAIT(1);
        else                CP_WAIT(0);
        __syncthreads();
        if (c + 2 < NCHUNK) load_stage((c + 2) % NSTAGE, c + 2);

        uint32_t st = sb + (uint32_t)(c % NSTAGE) * STAGE_BYTES;
        uint32_t sA = st, sB = st + 16384;

        #pragma unroll
        for (int ks = 0; ks < 4; ks++) {
            uint32_t a[2][4];
            #pragma unroll
            for (int i = 0; i < 2; i++) {
                uint32_t row = (uint32_t)(wm * 32 + i * 16) + a_r;
                uint32_t cgo = (((uint32_t)(ks * 2) + a_cg) * 16) ^ sx;
                ldsm_x4(a[i], sA + row * 128 + cgo);
            }
            #pragma unroll
            for (int g = 0; g < 4; g++) {
                uint32_t b[4];
                uint32_t row = (uint32_t)(wn * 64 + g * 16) + b_r;
                uint32_t cgo = (((uint32_t)(ks * 2) + b_cg) * 16) ^ sx;
                ldsm_x4(b, sB + row * 128 + cgo);
                #pragma unroll
                for (int i = 0; i < 2; i++) {
                    mma_f16(acc[i][g * 2 + 0], a[i], &b[0]);
                    mma_f16(acc[i][g * 2 + 1], a[i], &b[2]);
                }
            }
        }
    }

    const int g4 = lane >> 2, t4 = lane & 3;
    {
        uint8_t* C = (uint8_t*)Cout;
        const int nchunks = N >> 6;
        const int chunk = tile_n * 2 + wn;
        uint8_t* tb = C + (size_t)(tile_m * nchunks + chunk) * TILE_BYTES;
        #pragma unroll
        for (int i = 0; i < 2; i++) {
            int rl = wm * 32 + i * 16 + g4;
            uint32_t sw = (uint32_t)((rl & 7) << 4);
            #pragma unroll
            for (int j = 0; j < 8; j++) {
                int colg = tile_n * 128 + wn * 64 + j * 8 + t4 * 2;
                float bx = bias[colg], by = bias[colg + 1];
                __half2 v0 = __floats2half2_rn(acc[i][j][0] + bx, acc[i][j][1] + by);
                __half2 v1 = __floats2half2_rn(acc[i][j][2] + bx, acc[i][j][3] + by);
                uint32_t base = (uint32_t)(j * 16 + t4 * 4);
                *(__half2*)(tb + (((uint32_t)rl * 128 + base) ^ sw))       = v0;
                *(__half2*)(tb + (((uint32_t)(rl + 8) * 128 + base) ^ sw)) = v1;
            }
        }
    }
}

// ---------------------------------------------------------------------------
// Projection GEMM, BN=64 (measured equal to BN=128; kept). BM=128,
// 256 threads = 8 warps 4(M) x 2(N), warp tile 32 x 32, 72KB, 2 CTA/SM.
// ---------------------------------------------------------------------------
__global__ __launch_bounds__(256, 2) void gemm_hmma_proj(
    const uint8_t* __restrict__ A, const uint8_t* __restrict__ B,
    const float* __restrict__ bias, float* __restrict__ C, int N)
{
    extern __shared__ uint8_t smem[];
    const uint32_t sb = smem_u32(smem);

    const int tid  = threadIdx.x;
    const int lane = tid & 31;
    const int wid  = tid >> 5;
    const int wm   = wid >> 1;
    const int wn   = wid & 1;

    const int tile_n = blockIdx.x;
    const int tile_m = blockIdx.y;

    const size_t a0 = (size_t)tile_m * NCHUNK * TILE_BYTES;
    const size_t b0 = (size_t)(tile_n >> 1) * NCHUNK * TILE_BYTES
                    + (size_t)(tile_n & 1) * 8192;

    const uint32_t cp_off = (uint32_t)tid * 16;

    const uint32_t sx   = (uint32_t)((lane & 7) << 4);
    const uint32_t a_r  = (uint32_t)(((lane >> 3) & 1) * 8 + (lane & 7));
    const uint32_t a_cg = (uint32_t)(lane >> 4);
    const uint32_t b_r  = (uint32_t)(((lane >> 4) & 1) * 8 + (lane & 7));
    const uint32_t b_cg = (uint32_t)((lane >> 3) & 1);

    float acc[2][4][4];
    #pragma unroll
    for (int i = 0; i < 2; i++)
        #pragma unroll
        for (int j = 0; j < 4; j++)
            #pragma unroll
            for (int q = 0; q < 4; q++) acc[i][j][q] = 0.0f;

    auto load_stage = [&](int s, int c) {
        uint32_t st = sb + (uint32_t)s * STAGE_BYTES64;
        size_t ko = (size_t)c * TILE_BYTES;
        #pragma unroll
        for (int q = 0; q < 4; q++) {
            uint32_t o = cp_off + (uint32_t)q * 4096;
            cp16(st + o, A + a0 + ko + o);
        }
        #pragma unroll
        for (int q = 0; q < 2; q++) {
            uint32_t o = cp_off + (uint32_t)q * 4096;
            cp16(st + 16384 + o, B + b0 + ko + o);
        }
        CP_COMMIT();
    };

    load_stage(0, 0);
    load_stage(1, 1);

    for (int c = 0; c < NCHUNK; c++) {
        if (c < NCHUNK - 1) CP_WAIT(1);
        else                CP_WAIT(0);
        __syncthreads();
        if (c + 2 < NCHUNK) load_stage((c + 2) % NSTAGE, c + 2);

        uint32_t st = sb + (uint32_t)(c % NSTAGE) * STAGE_BYTES64;
        uint32_t sA = st, sB = st + 16384;

        #pragma unroll
        for (int ks = 0; ks < 4; ks++) {
            uint32_t a[2][4];
            #pragma unroll
            for (int i = 0; i < 2; i++) {
                uint32_t row = (uint32_t)(wm * 32 + i * 16) + a_r;
                uint32_t cgo = (((uint32_t)(ks * 2) + a_cg) * 16) ^ sx;
                ldsm_x4(a[i], sA + row * 128 + cgo);
            }
            #pragma unroll
            for (int g = 0; g < 2; g++) {
                uint32_t b[4];
                uint32_t row = (uint32_t)(wn * 32 + g * 16) + b_r;
                uint32_t cgo = (((uint32_t)(ks * 2) + b_cg) * 16) ^ sx;
                ldsm_x4(b, sB + row * 128 + cgo);
                #pragma unroll
                for (int i = 0; i < 2; i++) {
                    mma_f16(acc[i][g * 2 + 0], a[i], &b[0]);
                    mma_f16(acc[i][g * 2 + 1], a[i], &b[2]);
                }
            }
        }
    }

    const int g4 = lane >> 2, t4 = lane & 3;
    #pragma unroll
    for (int i = 0; i < 2; i++) {
        int row = tile_m * 128 + wm * 32 + i * 16 + g4;
        #pragma unroll
        for (int j = 0; j < 4; j++) {
            int col = tile_n * 64 + wn * 32 + j * 8 + t4 * 2;
            float bx = bias[col], by = bias[col + 1];
            float2 v0 = make_float2(acc[i][j][0] + bx, acc[i][j][1] + by);
            float2 v1 = make_float2(acc[i][j][2] + bx, acc[i][j][3] + by);
            *(float2*)(C + (size_t)row * N + col)       = v0;
            *(float2*)(C + (size_t)(row + 8) * N + col) = v1;
        }
    }
}

// ---------------------------------------------------------------------------
// MMA-based head attention, cp.async-pipelined: one warp per token,
// TWO slabs per warp (buf0=qkvh, buf1=qkvw). Both buffers' 72 x 4B lines
// are issued as cp.async up front (2 commit groups); buf1's DRAM latency
// hides behind buf0's compute. Arithmetic identical to round 8-14 version.
// Slab layout per buffer: Q[16x144] | K[16x144] | V[16x144] = 6912 B.
// ---------------------------------------------------------------------------
#define SLAB  6912
#define SLAB2 13824   // two buffers per warp

__global__ __launch_bounds__(256) void head_attn_mma(
    const uint8_t* __restrict__ qkvh, const uint8_t* __restrict__ qkvw,
    uint8_t* __restrict__ aout)
{
    extern __shared__ uint8_t sm[];
    const int lane = threadIdx.x & 31;
    const int warp = threadIdx.x >> 5;
    const int tok  = blockIdx.x * 8 + warp;
    const int tile = tok >> 7, r = tok & 127;

    const uint32_t s0 = smem_u32(sm) + (uint32_t)warp * SLAB2;  // buf0 slab
    const uint32_t s1 = s0 + SLAB;                               // buf1 slab

    // this lane's 4B within the token's 128B gmem row (swizzled)
    const uint32_t roff = (uint32_t)r * 128
        + ((((uint32_t)(lane >> 2)) * 16) ^ (((uint32_t)(r & 7)) << 4))
        + (uint32_t)(lane & 3) * 4;

    // zero V pad rows 12..15 of BOTH slabs (cp.async never touches them)
    #pragma unroll
    for (int i = 0; i < 5; i++) {
        int idx = lane + i * 32;
        if (idx < 144) {
            asm volatile("st.shared.u32 [%0], %1;" :: "r"(s0 + 4608 + 1728 + idx * 4), "r"(0u));
            asm volatile("st.shared.u32 [%0], %1;" :: "r"(s1 + 4608 + 1728 + idx * 4), "r"(0u));
        }
    }

    // Issue both buffers' loads: 36 cp.async x 4B per lane per buffer.
    {
        const uint8_t* b0p = qkvh + (size_t)tile * 36 * TILE_BYTES + roff;
        const uint8_t* b1p = qkvw + (size_t)tile * 36 * TILE_BYTES + roff;
        #pragma unroll
        for (int ch = 0; ch < 36; ch++) {
            uint32_t dst = s0 + (uint32_t)(ch / 12) * 2304
                         + (uint32_t)(ch % 12) * 144 + (uint32_t)lane * 4;
            cp4(dst, b0p + (size_t)ch * TILE_BYTES);
        }
        CP_COMMIT();
        #pragma unroll
        for (int ch = 0; ch < 36; ch++) {
            uint32_t dst = s1 + (uint32_t)(ch / 12) * 2304
                         + (uint32_t)(ch % 12) * 144 + (uint32_t)lane * 4;
            cp4(dst, b1p + (size_t)ch * TILE_BYTES);
        }
        CP_COMMIT();
    }

    // ldmatrix lane->offset maps (within a slab)
    const uint32_t mat = (uint32_t)lane >> 3, mrow = (uint32_t)lane & 7;
    const uint32_t qoff = (mrow + (mat & 1) * 8) * 144 + (mat >> 1) * 16;
    const uint32_t koff = 2304 + (mrow + (mat >> 1) * 8) * 144 + (mat & 1) * 16;
    const uint32_t voff = 4608 + (mrow + (mat & 1) * 8) * 144 + (mat >> 1) * 16;

    float o[8][4];
    #pragma unroll
    for (int j = 0; j < 8; j++)
        #pragma unroll
        for (int q = 0; q < 4; q++) o[j][q] = 0.0f;

    const bool mask_t1 = (lane & 3) >= 2;

    #pragma unroll
    for (int buf = 0; buf < 2; buf++) {
        if (buf == 0) CP_WAIT(1);     // buf0 group complete
        else          CP_WAIT(0);     // buf1 group complete
        __syncwarp();

        const uint32_t sbuf = buf ? s1 : s0;

        float s0r[4] = {0, 0, 0, 0}, s1r[4] = {0, 0, 0, 0};
        #pragma unroll
        for (int kc = 0; kc < 4; kc++) {
            uint32_t aq[4], bk[4];
            ldsm_x4(aq, sbuf + qoff + (uint32_t)kc * 32);
            ldsm_x4(bk, sbuf + koff + (uint32_t)kc * 32);
            mma_f16(s0r, aq, &bk[0]);
            mma_f16(s1r, aq, &bk[2]);
        }

        #pragma unroll
        for (int q = 0; q < 4; q++) {
            s0r[q] *= 0.125f;
            s1r[q] = mask_t1 ? -1e30f : s1r[q] * 0.125f;
        }

        float mx0 = fmaxf(fmaxf(s0r[0], s0r[1]), fmaxf(s1r[0], s1r[1]));
        float mx1 = fmaxf(fmaxf(s0r[2], s0r[3]), fmaxf(s1r[2], s1r[3]));
        mx0 = fmaxf(mx0, __shfl_xor_sync(0xffffffffu, mx0, 1));
        mx0 = fmaxf(mx0, __shfl_xor_sync(0xffffffffu, mx0, 2));
        mx1 = fmaxf(mx1, __shfl_xor_sync(0xffffffffu, mx1, 1));
        mx1 = fmaxf(mx1, __shfl_xor_sync(0xffffffffu, mx1, 2));

        s0r[0] = __expf(s0r[0] - mx0); s0r[1] = __expf(s0r[1] - mx0);
        s1r[0] = __expf(s1r[0] - mx0); s1r[1] = __expf(s1r[1] - mx0);
        s0r[2] = __expf(s0r[2] - mx1); s0r[3] = __expf(s0r[3] - mx1);
        s1r[2] = __expf(s1r[2] - mx1); s1r[3] = __expf(s1r[3] - mx1);

        float sum0 = s0r[0] + s0r[1] + s1r[0] + s1r[1];
        float sum1 = s0r[2] + s0r[3] + s1r[2] + s1r[3];
        sum0 += __shfl_xor_sync(0xffffffffu, sum0, 1);
        sum0 += __shfl_xor_sync(0xffffffffu, sum0, 2);
        sum1 += __shfl_xor_sync(0xffffffffu, sum1, 1);
        sum1 += __shfl_xor_sync(0xffffffffu, sum1, 2);
        float inv0 = 1.0f / sum0, inv1 = 1.0f / sum1;

        uint32_t pa[4];
        pa[0] = h2u(s0r[0] * inv0, s0r[1] * inv0);
        pa[1] = h2u(s0r[2] * inv1, s0r[3] * inv1);
        pa[2] = h2u(s1r[0] * inv0, s1r[1] * inv0);
        pa[3] = h2u(s1r[2] * inv1, s1r[3] * inv1);

        #pragma unroll
        for (int nb = 0; nb < 4; nb++) {
            uint32_t bv[4];
            ldsm_x4t(bv, sbuf + voff + (uint32_t)nb * 32);
            mma_f16(o[nb * 2 + 0], pa, &bv[0]);
            mma_f16(o[nb * 2 + 1], pa, &bv[2]);
        }
    }

    // ---- stage O (fp16) into slab0 Q region, then coalesced writes ----
    __syncwarp();
    {
        const uint32_t row0 = (uint32_t)(lane >> 2);
        const uint32_t colb = ((uint32_t)(lane & 3)) * 4;
        #pragma unroll
        for (int j = 0; j < 8; j++) {
            uint32_t c = (uint32_t)j * 16 + colb;
            uint32_t v0 = h2u(o[j][0], o[j][1]);
            uint32_t v1 = h2u(o[j][2], o[j][3]);
            asm volatile("st.shared.u32 [%0], %1;" :: "r"(s0 + row0 * 144 + c), "r"(v0));
            asm volatile("st.shared.u32 [%0], %1;" :: "r"(s0 + (row0 + 8) * 144 + c), "r"(v1));
        }
    }
    __syncwarp();
    {
        uint8_t* ob = aout + (size_t)tile * NCHUNK * TILE_BYTES + roff;
        #pragma unroll
        for (int h = 0; h < HEADS; h++) {
            uint32_t v;
            asm volatile("ld.shared.u32 %0, [%1];"
                         : "=r"(v) : "r"(s0 + (uint32_t)h * 144 + (uint32_t)lane * 4));
            *(uint32_t*)(ob + (size_t)h * TILE_BYTES) = v;
        }
    }
}

// ---------------------------------------------------------------------------
// Launch
// ---------------------------------------------------------------------------
extern "C" void kernel_launch(void* const* d_in, const int* in_sizes, int n_in,
                              void* d_out, int out_size)
{
    const float* x       = (const float*)d_in[0];
    const float* w_qkv_h = (const float*)d_in[1];
    const float* b_qkv_h = (const float*)d_in[2];
    const float* w_qkv_w = (const float*)d_in[3];
    const float* b_qkv_w = (const float*)d_in[4];
    const float* w_proj  = (const float*)d_in[5];
    const float* b_proj  = (const float*)d_in[6];
    float* out = (float*)d_out;

    uint8_t *A, *Bh, *Bw, *Bp, *qh, *qw, *Ao;
    cudaGetSymbolAddress((void**)&A,  g_A);
    cudaGetSymbolAddress((void**)&Bh, g_Bh);
    cudaGetSymbolAddress((void**)&Bw, g_Bw);
    cudaGetSymbolAddress((void**)&Bp, g_Bp);
    cudaGetSymbolAddress((void**)&qh, g_qkvh);
    cudaGetSymbolAddress((void**)&qw, g_qkvw);
    cudaGetSymbolAddress((void**)&Ao, g_Ao);

    const int qkv_smem  = NSTAGE * STAGE_BYTES;    // 98304 B
    const int proj_smem = NSTAGE * STAGE_BYTES64;  // 73728 B
    cudaFuncSetAttribute(gemm_hmma_qkv,
                         cudaFuncAttributeMaxDynamicSharedMemorySize, qkv_smem);
    cudaFuncSetAttribute(gemm_hmma_proj,
                         cudaFuncAttributeMaxDynamicSharedMemorySize, proj_smem);
    const int attn_smem = 8 * SLAB2;               // 110592 B
    cudaFuncSetAttribute(head_attn_mma,
                         cudaFuncAttributeMaxDynamicSharedMemorySize, attn_smem);

    dim3 qkv_grid(2 * DIM3 / 128, T_TOK / 128);   // (36, 256): both QKV GEMMs
    dim3 proj_grid(DIM / 64, T_TOK / 128);        // (12, 256): BN=64
    const int attn_grid = T_TOK / 8;              // 4096

    // All converts in one launch
    conv_all<<<14304, 256>>>(x, w_qkv_h, w_qkv_w, w_proj, A, Bh, Bw, Bp);

    // Both QKV GEMMs in one launch -> fp16 tiled qkv
    gemm_hmma_qkv<<<qkv_grid, 256, qkv_smem>>>(
        A, Bh, b_qkv_h, qh, Bw, b_qkv_w, qw, DIM3, DIM3 / 128);

    // Fused dual attention (tensor-core, cp.async-pipelined) -> fp16 A tiles
    head_attn_mma<<<attn_grid, 256, attn_smem>>>(qh, qw, Ao);

    // Projection (BN=64) -> fp32 output
    gemm_hmma_proj<<<proj_grid, 256, proj_smem>>>(Ao, Bp, b_proj, out, DIM);
}

// round 16
// speedup vs baseline: 1.0704x; 1.0704x over previous
#include <cuda_runtime.h>
#include <cuda_fp16.h>
#include <cstdint>

// Problem constants
#define T_TOK   32768        // 8*64*64 tokens
#define DIM     768
#define DIM3    2304
#define HEADS   12
#define HD      64
#define NCHUNK  12           // 768 / 64 (K chunks per tile row)
#define TILE_BYTES 16384     // 128 rows x 64 fp16 x 2B
#define NSTAGE  3
#define STAGE_QKV  32768     // A tile (16KB) + B tile (16KB)
#define STAGE_PROJ 24576     // A tile (16KB) + B half-tile (8KB)

// Scratch (fp16 tiled/swizzled)
__device__ uint8_t g_A  [(size_t)(T_TOK/128) * NCHUNK * TILE_BYTES];  // x tiles, 50MB
__device__ uint8_t g_Bh [(size_t)(DIM3/128) * NCHUNK * TILE_BYTES];   // 3.4MB
__device__ uint8_t g_Bw [(size_t)(DIM3/128) * NCHUNK * TILE_BYTES];
__device__ uint8_t g_Bp [(size_t)(DIM/128) * NCHUNK * TILE_BYTES];    // 1.2MB
__device__ uint8_t g_qkvh[(size_t)(T_TOK/128) * 36 * TILE_BYTES];     // 151MB
__device__ uint8_t g_qkvw[(size_t)(T_TOK/128) * 36 * TILE_BYTES];     // 151MB
__device__ uint8_t g_Ao [(size_t)(T_TOK/128) * NCHUNK * TILE_BYTES];  // attn out, 50MB

// ---------------------------------------------------------------------------
// PTX helpers (base-target: ldmatrix / mma.sync / cp.async.bulk / mbarrier)
// ---------------------------------------------------------------------------
__device__ __forceinline__ uint32_t smem_u32(const void* p) {
    uint32_t a;
    asm("{ .reg .u64 t; cvta.to.shared.u64 t, %1; cvt.u32.u64 %0, t; }"
        : "=r"(a) : "l"(p));
    return a;
}

__device__ __forceinline__ void ldsm_x4(uint32_t* r, uint32_t addr) {
    asm volatile("ldmatrix.sync.aligned.m8n8.x4.shared.b16 {%0,%1,%2,%3}, [%4];"
                 : "=r"(r[0]), "=r"(r[1]), "=r"(r[2]), "=r"(r[3]) : "r"(addr));
}

__device__ __forceinline__ void ldsm_x4t(uint32_t* r, uint32_t addr) {
    asm volatile("ldmatrix.sync.aligned.m8n8.x4.trans.shared.b16 {%0,%1,%2,%3}, [%4];"
                 : "=r"(r[0]), "=r"(r[1]), "=r"(r[2]), "=r"(r[3]) : "r"(addr));
}

__device__ __forceinline__ void mma_f16(float* d, const uint32_t* a, const uint32_t* b) {
    asm volatile(
        "mma.sync.aligned.m16n8k16.row.col.f32.f16.f16.f32 "
        "{%0,%1,%2,%3}, {%4,%5,%6,%7}, {%8,%9}, {%0,%1,%2,%3};"
        : "+f"(d[0]), "+f"(d[1]), "+f"(d[2]), "+f"(d[3])
        : "r"(a[0]), "r"(a[1]), "r"(a[2]), "r"(a[3]), "r"(b[0]), "r"(b[1]));
}

#define MBAR_INIT(addr, cnt) \
    asm volatile("mbarrier.init.shared.b64 [%0], %1;" :: "r"(addr), "r"(cnt) : "memory")

#define MBAR_EXPECT_TX(addr, bytes) \
    asm volatile("mbarrier.arrive.expect_tx.shared.b64 _, [%0], %1;" \
                 :: "r"(addr), "r"(bytes) : "memory")

#define MBAR_WAIT(addr, parity) do { \
    asm volatile("{\n\t.reg .pred P;\n\t" \
        "W0_%=:\n\t" \
        "mbarrier.try_wait.parity.shared::cta.b64 P, [%0], %1, 0x989680;\n\t" \
        "@P bra W1_%=;\n\t" \
        "bra W0_%=;\n\t" \
        "W1_%=:\n\t}" \
        :: "r"(addr), "r"(parity) : "memory"); \
} while (0)

__device__ __forceinline__ void bulk_copy(uint32_t dst_smem, const void* src,
                                          uint32_t bytes, uint32_t mbar) {
    asm volatile(
        "cp.async.bulk.shared::cluster.global.mbarrier::complete_tx::bytes "
        "[%0], [%1], %2, [%3];"
        :: "r"(dst_smem), "l"(src), "r"(bytes), "r"(mbar) : "memory");
}

__device__ __forceinline__ uint32_t h2u(float x, float y) {
    __half2 h = __floats2half2_rn(x, y);
    return *(uint32_t*)&h;
}

// ---------------------------------------------------------------------------
// Converts: fp32 -> fp16, pre-tiled 16KB blocks, SW128-style swizzle:
// off(r, c16) = (r*128 + c16*16) ^ ((r&7)<<4). Tile = 128 rows x 64 fp16.
// All four converts fused into ONE launch, dispatched by blockIdx range.
// ---------------------------------------------------------------------------
union HF8 { __half h[8]; uint4 u; };

__device__ __forceinline__ void conv_a_body(
    int idx, const float* __restrict__ in, uint8_t* __restrict__ dst)
{
    int m = idx / 96;                               // 96 units per row (768/8)
    int u = idx - m * 96;
    const float* p = in + (size_t)m * DIM + u * 8;
    float4 v0 = *(const float4*)p;
    float4 v1 = *(const float4*)(p + 4);
    float f[8] = {v0.x, v0.y, v0.z, v0.w, v1.x, v1.y, v1.z, v1.w};
    HF8 h;
    #pragma unroll
    for (int i = 0; i < 8; i++) h.h[i] = __float2half_rn(f[i]);
    int mtile = m >> 7, r = m & 127, chunk = u >> 3, c16 = u & 7;
    uint32_t off = (uint32_t)(r * 128 + c16 * 16) ^ (uint32_t)((r & 7) << 4);
    *(uint4*)(dst + (size_t)(mtile * NCHUNK + chunk) * TILE_BYTES + off) = h.u;
}

__device__ __forceinline__ void conv_b_body(
    int idx, const float* __restrict__ w, uint8_t* __restrict__ dst, int N)
{
    int n = idx / 96;
    int u = idx - n * 96;
    int k0 = u * 8;
    HF8 h;
    #pragma unroll
    for (int i = 0; i < 8; i++)
        h.h[i] = __float2half_rn(w[(size_t)(k0 + i) * N + n]);
    int ntile = n >> 7, r = n & 127, chunk = u >> 3, c16 = u & 7;
    uint32_t off = (uint32_t)(r * 128 + c16 * 16) ^ (uint32_t)((r & 7) << 4);
    *(uint4*)(dst + (size_t)(ntile * NCHUNK + chunk) * TILE_BYTES + off) = h.u;
}

// blocks: [0,12288) A | [12288,13152) Bh | [13152,14016) Bw | [14016,14304) Bp
__global__ __launch_bounds__(256) void conv_all(
    const float* __restrict__ x,
    const float* __restrict__ w_qkv_h, const float* __restrict__ w_qkv_w,
    const float* __restrict__ w_proj,
    uint8_t* __restrict__ A, uint8_t* __restrict__ Bh,
    uint8_t* __restrict__ Bw, uint8_t* __restrict__ Bp)
{
    int b = blockIdx.x;
    if (b < 12288) {
        conv_a_body(b * 256 + threadIdx.x, x, A);
    } else if (b < 13152) {
        conv_b_body((b - 12288) * 256 + threadIdx.x, w_qkv_h, Bh, DIM3);
    } else if (b < 14016) {
        conv_b_body((b - 13152) * 256 + threadIdx.x, w_qkv_w, Bw, DIM3);
    } else {
        conv_b_body((b - 14016) * 256 + threadIdx.x, w_proj, Bp, DIM);
    }
}

// ---------------------------------------------------------------------------
// Bulk-copy HMMA GEMM (QKV): C = A @ B^T + bias, fp16 tiled+swizzled out.
// BM=BN=128, 128 threads = 4 warps 2(M) x 2(N), warp tile 64 x 64.
// 3-stage ring; loads are cp.async.bulk issued by thread 0 + mbarrier waits
// (removes the 4096 LDGSTS/chunk/SM issue saturation that capped tensor at
// 60% in rounds 10-13). One __syncthreads per chunk, ~97KB smem, 2 CTA/SM.
// Dual-output mode via nsplit.
// smem: full[3] mbarriers at sb+0/8/16; tiles at sb+1024.
// ---------------------------------------------------------------------------
__global__ __launch_bounds__(128, 2) void gemm_bulk_qkv(
    const uint8_t* __restrict__ A,
    const uint8_t* __restrict__ B,  const float* __restrict__ bias,  void* Cout,
    const uint8_t* __restrict__ B2, const float* __restrict__ bias2, void* Cout2,
    int N, int nsplit)
{
    extern __shared__ uint8_t smem[];
    const uint32_t sb    = smem_u32(smem);
    const uint32_t FULLB = sb;             // 3 mbarriers
    const uint32_t TILES = sb + 1024;

    const int tid  = threadIdx.x;
    const int lane = tid & 31;
    const int wid  = tid >> 5;          // 0..3
    const int wm   = wid >> 1;          // 0..1 -> M (64 rows each)
    const int wn   = wid & 1;           // 0..1 -> N (64 cols each)

    int tile_n = blockIdx.x;
    const int tile_m = blockIdx.y;
    if (tile_n >= nsplit) { tile_n -= nsplit; B = B2; bias = bias2; Cout = Cout2; }

    const size_t a0 = (size_t)tile_m * NCHUNK * TILE_BYTES;
    const size_t b0 = (size_t)tile_n * NCHUNK * TILE_BYTES;

    if (tid == 0) {
        MBAR_INIT(FULLB + 0, 1);
        MBAR_INIT(FULLB + 8, 1);
        MBAR_INIT(FULLB + 16, 1);
        asm volatile("fence.proxy.async.shared::cta;" ::: "memory");
    }
    __syncthreads();

    auto issue = [&](int s, int c) {
        uint32_t mb = FULLB + (uint32_t)s * 8;
        uint32_t st = TILES + (uint32_t)s * STAGE_QKV;
        size_t ko = (size_t)c * TILE_BYTES;
        MBAR_EXPECT_TX(mb, STAGE_QKV);
        bulk_copy(st,         A + a0 + ko, TILE_BYTES, mb);
        bulk_copy(st + 16384, B + b0 + ko, TILE_BYTES, mb);
    };

    // ldmatrix lane maps (verified rounds 4-15)
    const uint32_t sx   = (uint32_t)((lane & 7) << 4);
    const uint32_t a_r  = (uint32_t)(((lane >> 3) & 1) * 8 + (lane & 7));
    const uint32_t a_cg = (uint32_t)(lane >> 4);
    const uint32_t b_r  = (uint32_t)(((lane >> 4) & 1) * 8 + (lane & 7));
    const uint32_t b_cg = (uint32_t)((lane >> 3) & 1);

    // 64x64 warp tile: 4 m16 x 8 n8 fragments
    float acc[4][8][4];
    #pragma unroll
    for (int i = 0; i < 4; i++)
        #pragma unroll
        for (int j = 0; j < 8; j++)
            #pragma unroll
            for (int q = 0; q < 4; q++) acc[i][j][q] = 0.0f;

    // Prologue: chunks 0,1; chunk 2 issued at iter 0.
    if (tid == 0) { issue(0, 0); issue(1, 1); }

    for (int c = 0; c < NCHUNK; c++) {
        MBAR_WAIT(FULLB + (uint32_t)(c % NSTAGE) * 8, (c / NSTAGE) & 1);
        __syncthreads();
        // Refill stage (c+2)%3 = (c-1)%3 with chunk c+2: compute of chunk c-1
        // finished before this iteration's sync, so the overwrite is safe.
        if (tid == 0 && c + 2 < NCHUNK) issue((c + 2) % NSTAGE, c + 2);

        uint32_t st = TILES + (uint32_t)(c % NSTAGE) * STAGE_QKV;
        uint32_t sA = st, sB = st + 16384;

        #pragma unroll
        for (int ks = 0; ks < 4; ks++) {
            uint32_t a[4][4];
            #pragma unroll
            for (int i = 0; i < 4; i++) {
                uint32_t row = (uint32_t)(wm * 64 + i * 16) + a_r;
                uint32_t cgo = (((uint32_t)(ks * 2) + a_cg) * 16) ^ sx;
                ldsm_x4(a[i], sA + row * 128 + cgo);
            }
            #pragma unroll
            for (int g = 0; g < 4; g++) {
                uint32_t b[4];
                uint32_t row = (uint32_t)(wn * 64 + g * 16) + b_r;
                uint32_t cgo = (((uint32_t)(ks * 2) + b_cg) * 16) ^ sx;
                ldsm_x4(b, sB + row * 128 + cgo);
                #pragma unroll
                for (int i = 0; i < 4; i++) {
                    mma_f16(acc[i][g * 2 + 0], a[i], &b[0]);
                    mma_f16(acc[i][g * 2 + 1], a[i], &b[2]);
                }
            }
        }
        __syncthreads();   // all warps done with stage c%3 before its refill
                           // (issued at iter c+1) can land
    }

    // ---- epilogue: fp16 tiled+swizzled (verified round 11) ----
    const int g4 = lane >> 2, t4 = lane & 3;
    {
        uint8_t* C = (uint8_t*)Cout;
        const int nchunks = N >> 6;
        const int chunk = tile_n * 2 + wn;
        uint8_t* tb = C + (size_t)(tile_m * nchunks + chunk) * TILE_BYTES;
        #pragma unroll
        for (int i = 0; i < 4; i++) {
            int rl = wm * 64 + i * 16 + g4;        // 0..127 within tile
            uint32_t sw = (uint32_t)((rl & 7) << 4);
            #pragma unroll
            for (int j = 0; j < 8; j++) {
                int colg = tile_n * 128 + wn * 64 + j * 8 + t4 * 2;
                float bx = bias[colg], by = bias[colg + 1];
                __half2 v0 = __floats2half2_rn(acc[i][j][0] + bx, acc[i][j][1] + by);
                __half2 v1 = __floats2half2_rn(acc[i][j][2] + bx, acc[i][j][3] + by);
                uint32_t base = (uint32_t)(j * 16 + t4 * 4);
                *(__half2*)(tb + (((uint32_t)rl * 128 + base) ^ sw))       = v0;
                *(__half2*)(tb + (((uint32_t)(rl + 8) * 128 + base) ^ sw)) = v1;
            }
        }
    }
}

// ---------------------------------------------------------------------------
// Bulk-copy HMMA GEMM (projection): BN=64, fp32 row-major out.
// BM=128, 128 threads = 4 warps 2(M) x 2(N), warp tile 64 x 32.
// Same bulk+mbarrier 3-stage pipeline; stage 24KB, ~73KB smem, 2 CTA/SM.
// ---------------------------------------------------------------------------
__global__ __launch_bounds__(128, 2) void gemm_bulk_proj(
    const uint8_t* __restrict__ A, const uint8_t* __restrict__ B,
    const float* __restrict__ bias, float* __restrict__ C, int N)
{
    extern __shared__ uint8_t smem[];
    const uint32_t sb    = smem_u32(smem);
    const uint32_t FULLB = sb;
    const uint32_t TILES = sb + 1024;

    const int tid  = threadIdx.x;
    const int lane = tid & 31;
    const int wid  = tid >> 5;
    const int wm   = wid >> 1;          // 0..1 -> M (64 rows each)
    const int wn   = wid & 1;           // 0..1 -> N (32 cols each)

    const int tile_n = blockIdx.x;      // 64-column tiles
    const int tile_m = blockIdx.y;

    const size_t a0 = (size_t)tile_m * NCHUNK * TILE_BYTES;
    // B half-tile: 64 rows of the 128-row tile; swizzle self-consistent.
    const size_t b0 = (size_t)(tile_n >> 1) * NCHUNK * TILE_BYTES
                    + (size_t)(tile_n & 1) * 8192;

    if (tid == 0) {
        MBAR_INIT(FULLB + 0, 1);
        MBAR_INIT(FULLB + 8, 1);
        MBAR_INIT(FULLB + 16, 1);
        asm volatile("fence.proxy.async.shared::cta;" ::: "memory");
    }
    __syncthreads();

    auto issue = [&](int s, int c) {
        uint32_t mb = FULLB + (uint32_t)s * 8;
        uint32_t st = TILES + (uint32_t)s * STAGE_PROJ;
        size_t ko = (size_t)c * TILE_BYTES;
        MBAR_EXPECT_TX(mb, STAGE_PROJ);
        bulk_copy(st,         A + a0 + ko, TILE_BYTES, mb);
        bulk_copy(st + 16384, B + b0 + ko, 8192, mb);
    };

    const uint32_t sx   = (uint32_t)((lane & 7) << 4);
    const uint32_t a_r  = (uint32_t)(((lane >> 3) & 1) * 8 + (lane & 7));
    const uint32_t a_cg = (uint32_t)(lane >> 4);
    const uint32_t b_r  = (uint32_t)(((lane >> 4) & 1) * 8 + (lane & 7));
    const uint32_t b_cg = (uint32_t)((lane >> 3) & 1);

    // 64x32 warp tile: 4 m16 x 4 n8 fragments
    float acc[4][4][4];
    #pragma unroll
    for (int i = 0; i < 4; i++)
        #pragma unroll
        for (int j = 0; j < 4; j++)
            #pragma unroll
            for (int q = 0; q < 4; q++) acc[i][j][q] = 0.0f;

    if (tid == 0) { issue(0, 0); issue(1, 1); }

    for (int c = 0; c < NCHUNK; c++) {
        MBAR_WAIT(FULLB + (uint32_t)(c % NSTAGE) * 8, (c / NSTAGE) & 1);
        __syncthreads();
        if (tid == 0 && c + 2 < NCHUNK) issue((c + 2) % NSTAGE, c + 2);

        uint32_t st = TILES + (uint32_t)(c % NSTAGE) * STAGE_PROJ;
        uint32_t sA = st, sB = st + 16384;

        #pragma unroll
        for (int ks = 0; ks < 4; ks++) {
            uint32_t a[4][4];
            #pragma unroll
            for (int i = 0; i < 4; i++) {
                uint32_t row = (uint32_t)(wm * 64 + i * 16) + a_r;
                uint32_t cgo = (((uint32_t)(ks * 2) + a_cg) * 16) ^ sx;
                ldsm_x4(a[i], sA + row * 128 + cgo);
            }
            #pragma unroll
            for (int g = 0; g < 2; g++) {
                uint32_t b[4];
                uint32_t row = (uint32_t)(wn * 32 + g * 16) + b_r;
                uint32_t cgo = (((uint32_t)(ks * 2) + b_cg) * 16) ^ sx;
                ldsm_x4(b, sB + row * 128 + cgo);
                #pragma unroll
                for (int i = 0; i < 4; i++) {
                    mma_f16(acc[i][g * 2 + 0], a[i], &b[0]);
                    mma_f16(acc[i][g * 2 + 1], a[i], &b[2]);
                }
            }
        }
        __syncthreads();
    }

    // ---- epilogue: fp32 row-major ----
    const int g4 = lane >> 2, t4 = lane & 3;
    #pragma unroll
    for (int i = 0; i < 4; i++) {
        int row = tile_m * 128 + wm * 64 + i * 16 + g4;
        #pragma unroll
        for (int j = 0; j < 4; j++) {
            int col = tile_n * 64 + wn * 32 + j * 8 + t4 * 2;
            float bx = bias[col], by = bias[col + 1];
            float2 v0 = make_float2(acc[i][j][0] + bx, acc[i][j][1] + by);
            float2 v1 = make_float2(acc[i][j][2] + bx, acc[i][j][3] + by);
            *(float2*)(C + (size_t)row * N + col)       = v0;
            *(float2*)(C + (size_t)(row + 8) * N + col) = v1;
        }
    }
}

// ---------------------------------------------------------------------------
// MMA-based head attention (verified round 8, reverted from round-15 cp.async
// variant which regressed): one warp per token, heads padded 12->16;
// S = Q.K^T (8 HMMA), quad softmax, O = P.V (8 HMMA), both qkv buffers
// accumulated; writes fp16 proj-A tiles.
// ---------------------------------------------------------------------------
#define SLAB 6912    // 3 * 16 * 144

__global__ __launch_bounds__(256) void head_attn_mma(
    const uint8_t* __restrict__ qkvh, const uint8_t* __restrict__ qkvw,
    uint8_t* __restrict__ aout)
{
    extern __shared__ uint8_t sm[];
    const int lane = threadIdx.x & 31;
    const int warp = threadIdx.x >> 5;
    const int tok  = blockIdx.x * 8 + warp;
    const int tile = tok >> 7, r = tok & 127;

    const uint32_t sQ = smem_u32(sm) + (uint32_t)warp * SLAB;
    const uint32_t sK = sQ + 2304;
    const uint32_t sV = sQ + 4608;

    const uint32_t roff = (uint32_t)r * 128
        + ((((uint32_t)(lane >> 2)) * 16) ^ (((uint32_t)(r & 7)) << 4))
        + (uint32_t)(lane & 3) * 4;

    #pragma unroll
    for (int i = 0; i < 5; i++) {
        int idx = lane + i * 32;
        if (idx < 144)
            asm volatile("st.shared.u32 [%0], %1;" :: "r"(sV + 1728 + idx * 4), "r"(0u));
    }

    const uint32_t mat = (uint32_t)lane >> 3, mrow = (uint32_t)lane & 7;
    const uint32_t qa = sQ + (mrow + (mat & 1) * 8) * 144 + (mat >> 1) * 16;
    const uint32_t kb = sK + (mrow + (mat >> 1) * 8) * 144 + (mat & 1) * 16;
    const uint32_t vb = sV + (mrow + (mat & 1) * 8) * 144 + (mat >> 1) * 16;

    float o[8][4];
    #pragma unroll
    for (int j = 0; j < 8; j++)
        #pragma unroll
        for (int q = 0; q < 4; q++) o[j][q] = 0.0f;

    const bool mask_t1 = (lane & 3) >= 2;

    #pragma unroll
    for (int buf = 0; buf < 2; buf++) {
        const uint8_t* base = (buf ? qkvw : qkvh)
                            + (size_t)tile * 36 * TILE_BYTES + roff;
        __syncwarp();
        #pragma unroll
        for (int ch = 0; ch < 36; ch++) {
            uint32_t v = *(const uint32_t*)(base + (size_t)ch * TILE_BYTES);
            uint32_t dst = sQ + (uint32_t)(ch / 12) * 2304
                         + (uint32_t)(ch % 12) * 144 + (uint32_t)lane * 4;
            asm volatile("st.shared.u32 [%0], %1;" :: "r"(dst), "r"(v));
        }
        __syncwarp();

        float s0[4] = {0, 0, 0, 0}, s1[4] = {0, 0, 0, 0};
        #pragma unroll
        for (int kc = 0; kc < 4; kc++) {
            uint32_t aq[4], bk[4];
            ldsm_x4(aq, qa + (uint32_t)kc * 32);
            ldsm_x4(bk, kb + (uint32_t)kc * 32);
            mma_f16(s0, aq, &bk[0]);
            mma_f16(s1, aq, &bk[2]);
        }

        #pragma unroll
        for (int q = 0; q < 4; q++) {
            s0[q] *= 0.125f;
            s1[q] = mask_t1 ? -1e30f : s1[q] * 0.125f;
        }

        float mx0 = fmaxf(fmaxf(s0[0], s0[1]), fmaxf(s1[0], s1[1]));
        float mx1 = fmaxf(fmaxf(s0[2], s0[3]), fmaxf(s1[2], s1[3]));
        mx0 = fmaxf(mx0, __shfl_xor_sync(0xffffffffu, mx0, 1));
        mx0 = fmaxf(mx0, __shfl_xor_sync(0xffffffffu, mx0, 2));
        mx1 = fmaxf(mx1, __shfl_xor_sync(0xffffffffu, mx1, 1));
        mx1 = fmaxf(mx1, __shfl_xor_sync(0xffffffffu, mx1, 2));

        s0[0] = __expf(s0[0] - mx0); s0[1] = __expf(s0[1] - mx0);
        s1[0] = __expf(s1[0] - mx0); s1[1] = __expf(s1[1] - mx0);
        s0[2] = __expf(s0[2] - mx1); s0[3] = __expf(s0[3] - mx1);
        s1[2] = __expf(s1[2] - mx1); s1[3] = __expf(s1[3] - mx1);

        float sum0 = s0[0] + s0[1] + s1[0] + s1[1];
        float sum1 = s0[2] + s0[3] + s1[2] + s1[3];
        sum0 += __shfl_xor_sync(0xffffffffu, sum0, 1);
        sum0 += __shfl_xor_sync(0xffffffffu, sum0, 2);
        sum1 += __shfl_xor_sync(0xffffffffu, sum1, 1);
        sum1 += __shfl_xor_sync(0xffffffffu, sum1, 2);
        float inv0 = 1.0f / sum0, inv1 = 1.0f / sum1;

        uint32_t pa[4];
        pa[0] = h2u(s0[0] * inv0, s0[1] * inv0);
        pa[1] = h2u(s0[2] * inv1, s0[3] * inv1);
        pa[2] = h2u(s1[0] * inv0, s1[1] * inv0);
        pa[3] = h2u(s1[2] * inv1, s1[3] * inv1);

        #pragma unroll
        for (int nb = 0; nb < 4; nb++) {
            uint32_t bv[4];
            ldsm_x4t(bv, vb + (uint32_t)nb * 32);
            mma_f16(o[nb * 2 + 0], pa, &bv[0]);
            mma_f16(o[nb * 2 + 1], pa, &bv[2]);
        }
    }

    __syncwarp();
    {
        const uint32_t row0 = (uint32_t)(lane >> 2);
        const uint32_t colb = ((uint32_t)(lane & 3)) * 4;
        #pragma unroll
        for (int j = 0; j < 8; j++) {
            uint32_t c = (uint32_t)j * 16 + colb;
            uint32_t v0 = h2u(o[j][0], o[j][1]);
            uint32_t v1 = h2u(o[j][2], o[j][3]);
            asm volatile("st.shared.u32 [%0], %1;" :: "r"(sQ + row0 * 144 + c), "r"(v0));
            asm volatile("st.shared.u32 [%0], %1;" :: "r"(sQ + (row0 + 8) * 144 + c), "r"(v1));
        }
    }
    __syncwarp();
    {
        uint8_t* ob = aout + (size_t)tile * NCHUNK * TILE_BYTES + roff;
        #pragma unroll
        for (int h = 0; h < HEADS; h++) {
            uint32_t v;
            asm volatile("ld.shared.u32 %0, [%1];"
                         : "=r"(v) : "r"(sQ + (uint32_t)h * 144 + (uint32_t)lane * 4));
            *(uint32_t*)(ob + (size_t)h * TILE_BYTES) = v;
        }
    }
}

// ---------------------------------------------------------------------------
// Launch
// ---------------------------------------------------------------------------
extern "C" void kernel_launch(void* const* d_in, const int* in_sizes, int n_in,
                              void* d_out, int out_size)
{
    const float* x       = (const float*)d_in[0];
    const float* w_qkv_h = (const float*)d_in[1];
    const float* b_qkv_h = (const float*)d_in[2];
    const float* w_qkv_w = (const float*)d_in[3];
    const float* b_qkv_w = (const float*)d_in[4];
    const float* w_proj  = (const float*)d_in[5];
    const float* b_proj  = (const float*)d_in[6];
    float* out = (float*)d_out;

    uint8_t *A, *Bh, *Bw, *Bp, *qh, *qw, *Ao;
    cudaGetSymbolAddress((void**)&A,  g_A);
    cudaGetSymbolAddress((void**)&Bh, g_Bh);
    cudaGetSymbolAddress((void**)&Bw, g_Bw);
    cudaGetSymbolAddress((void**)&Bp, g_Bp);
    cudaGetSymbolAddress((void**)&qh, g_qkvh);
    cudaGetSymbolAddress((void**)&qw, g_qkvw);
    cudaGetSymbolAddress((void**)&Ao, g_Ao);

    const int qkv_smem  = 1024 + NSTAGE * STAGE_QKV;    // 99328 B
    const int proj_smem = 1024 + NSTAGE * STAGE_PROJ;   // 74752 B
    cudaFuncSetAttribute(gemm_bulk_qkv,
                         cudaFuncAttributeMaxDynamicSharedMemorySize, qkv_smem);
    cudaFuncSetAttribute(gemm_bulk_proj,
                         cudaFuncAttributeMaxDynamicSharedMemorySize, proj_smem);
    const int attn_smem = 8 * SLAB;                     // 55296 B
    cudaFuncSetAttribute(head_attn_mma,
                         cudaFuncAttributeMaxDynamicSharedMemorySize, attn_smem);

    dim3 qkv_grid(2 * DIM3 / 128, T_TOK / 128);   // (36, 256): both QKV GEMMs
    dim3 proj_grid(DIM / 64, T_TOK / 128);        // (12, 256): BN=64
    const int attn_grid = T_TOK / 8;              // 4096

    // All converts in one launch
    conv_all<<<14304, 256>>>(x, w_qkv_h, w_qkv_w, w_proj, A, Bh, Bw, Bp);

    // Both QKV GEMMs in one launch -> fp16 tiled qkv
    gemm_bulk_qkv<<<qkv_grid, 128, qkv_smem>>>(
        A, Bh, b_qkv_h, qh, Bw, b_qkv_w, qw, DIM3, DIM3 / 128);

    // Fused dual attention (tensor-core) -> fp16 proj-A tiles
    head_attn_mma<<<attn_grid, 256, attn_smem>>>(qh, qw, Ao);

    // Projection (BN=64, bulk pipeline) -> fp32 output
    gemm_bulk_proj<<<proj_grid, 128, proj_smem>>>(Ao, Bp, b_proj, out, DIM);
}